// round 5
// baseline (speedup 1.0000x reference)
#include <cuda_runtime.h>
#include <cuda_fp16.h>
#include <math.h>
#include <stdint.h>

// ============================================================================
// Problem constants
// ============================================================================
#define B_  4096
#define IN_ 512
#define H_  1024
#define O_  256
#define L_  2
#define G_  3
#define NH  (G_ * O_)        // 768 per head
#define NHEADS3 (3 * NH)     // 2304 fused head columns

// ============================================================================
// GEMM tiling (mma.sync m16n8k16 f16, ldmatrix feeds)
//   A: half, cp.async, 3-stage ring. W: fp32 LDG -> cvt -> STS, 2 buffers.
// ============================================================================
#define BM 128
#define BN 128
#define BK 32
#define PH 40                           // smem pitch in halves (80 B rows)
#define ATB (BM * PH * 2)               // 10240 B per tile buffer
#define WBASE (3 * ATB)                 // W buffers start after 3 A buffers
#define SMEM_BYTES (5 * ATB)            // 51200

// ============================================================================
// Scratch (device globals)
// ============================================================================
static __device__ __align__(256) __half g_xh   [(size_t)B_ * IN_];
static __device__ __align__(256) __half g_hidh [(size_t)L_ * B_ * H_];
static __device__ __align__(256) __half g_h1h  [(size_t)B_ * H_];
static __device__ __align__(256) float  g_gi   [(size_t)B_ * 3 * H_];
static __device__ __align__(256) float  g_gh   [(size_t)B_ * 3 * H_];
static __device__ __align__(256) __half g_h2h  [(size_t)B_ * H_];
static __device__ __align__(256) __half g_houth[(size_t)B_ * H_];

// ============================================================================
// PTX helpers
// ============================================================================
__device__ __forceinline__ void cp_async16(uint32_t saddr, const void* gptr) {
    asm volatile("cp.async.cg.shared.global [%0], [%1], 16;"
                 :: "r"(saddr), "l"(gptr) : "memory");
}
__device__ __forceinline__ void cp_commit() {
    asm volatile("cp.async.commit_group;" ::: "memory");
}
__device__ __forceinline__ void cp_wait1() {
    asm volatile("cp.async.wait_group 1;" ::: "memory");
}
__device__ __forceinline__ void cp_wait0() {
    asm volatile("cp.async.wait_group 0;" ::: "memory");
}

#define LDSM4(r, a) \
    asm volatile("ldmatrix.sync.aligned.m8n8.x4.shared.b16 {%0,%1,%2,%3}, [%4];" \
        : "=r"((r)[0]), "=r"((r)[1]), "=r"((r)[2]), "=r"((r)[3]) : "r"(a))

__device__ __forceinline__ void mma_f16(float c[4], const uint32_t a[4],
                                        uint32_t b0, uint32_t b1) {
    asm volatile(
        "mma.sync.aligned.m16n8k16.row.col.f32.f16.f16.f32 "
        "{%0,%1,%2,%3}, {%4,%5,%6,%7}, {%8,%9}, {%0,%1,%2,%3};"
        : "+f"(c[0]), "+f"(c[1]), "+f"(c[2]), "+f"(c[3])
        : "r"(a[0]), "r"(a[1]), "r"(a[2]), "r"(a[3]), "r"(b0), "r"(b1));
}

__device__ __forceinline__ uint32_t h2_to_u32(__half2 h) {
    return *reinterpret_cast<uint32_t*>(&h);
}

// ============================================================================
// Weight table: up to 3 column-segments (for fused MDN heads), each with its
// own fp32 weight matrix [segN, K] and fp32 bias [segN].
// ============================================================================
struct WTab {
    const float* w[3];
    const float* b[3];
    int segN;            // columns per segment (== N for single-segment GEMMs)
};

// ============================================================================
// GEMM: C[M,N] = A[M,K] @ W[N,K]^T + bias[N]
//   A: __half row-major (K contiguous). W: fp32 row-major (original inputs).
//   act 0: fp32 out to Cf (stride N)
//   act 1: relu -> __half out to Ch (stride N)
//   act 2: fused-heads: seg = col/segN, softplus on seg 1,
//          out = Cf + seg*M*segN + row*segN + (col - seg*segN)
// ============================================================================
__global__ __launch_bounds__(256, 2)
void gemm_f16(const __half* __restrict__ A, const WTab wt,
              const float* __restrict__ Abias_unused,
              float* __restrict__ Cf, __half* __restrict__ Ch,
              int M, int N, int K, int act)
{
    extern __shared__ char smem_raw[];
    const uint32_t sbase = (uint32_t)__cvta_generic_to_shared(smem_raw);

    const int tid  = threadIdx.x;
    const int lane = tid & 31;
    const int wid  = tid >> 5;
    const int wm   = wid & 1;            // 2 warps along M (64 rows)
    const int wn   = wid >> 1;           // 4 warps along N (32 cols)
    const int bm   = blockIdx.y * BM;
    const int bn   = blockIdx.x * BN;

    // Weight segment for this block's columns
    const int segB = bn / wt.segN;
    const float* __restrict__ Wp = wt.w[segB];
    const int wrow0 = bn - segB * wt.segN;

    float acc[4][4][4];
#pragma unroll
    for (int i = 0; i < 4; ++i)
#pragma unroll
        for (int j = 0; j < 4; ++j)
#pragma unroll
            for (int q = 0; q < 4; ++q) acc[i][j][q] = 0.f;

    const int nT = K / BK;

    // ---- A loads: cp.async, 2 x 16B per thread per stage ----
    auto issueA = [&](int stg, int kt) {
        uint32_t sa = sbase + stg * ATB;
#pragma unroll
        for (int i = 0; i < 2; ++i) {
            int idx = tid + i * 256;
            int row = idx >> 2;
            int c8  = (idx & 3) << 3;
            cp_async16(sa + (uint32_t)(row * PH + c8) * 2,
                       A + (size_t)(bm + row) * K + kt + c8);
        }
        cp_commit();
    };

    // ---- W loads: fp32 LDG.128 into regs (4 float4/thread/stage) ----
    // idx = tid + i*256; row = idx>>3 (0..127? no: 1024 idx -> row=idx>>3 0..127)
    float4 wreg[4];
    auto ldgW = [&](int kt) {
#pragma unroll
        for (int i = 0; i < 4; ++i) {
            int idx = tid + i * 256;
            int row = idx >> 3;
            int c4  = (idx & 7) << 2;
            wreg[i] = *reinterpret_cast<const float4*>(
                Wp + (size_t)(wrow0 + row) * K + kt + c4);
        }
    };
    auto stsW = [&](int buf) {
        char* wb = smem_raw + WBASE + buf * ATB;
#pragma unroll
        for (int i = 0; i < 4; ++i) {
            int idx = tid + i * 256;
            int row = idx >> 3;
            int c4  = (idx & 7) << 2;
            uint2 u;
            u.x = h2_to_u32(__floats2half2_rn(wreg[i].x, wreg[i].y));
            u.y = h2_to_u32(__floats2half2_rn(wreg[i].z, wreg[i].w));
            *reinterpret_cast<uint2*>(wb + (size_t)(row * PH + c4) * 2) = u;
        }
    };

    // ---- Prologue ----
    issueA(0, 0);
    issueA(1, BK);
    ldgW(0);
    stsW(0);
    ldgW(BK);

    // ---- ldmatrix lane addressing (pitch PH halves) ----
    const uint32_t aOff = (uint32_t)(((wm * 64 + (lane & 15)) * PH +
                                      ((lane >> 4) << 3)) * 2);
    const uint32_t bOff = (uint32_t)(((wn * 32 + ((lane >> 4) << 3) + (lane & 7)) * PH +
                                      (((lane >> 3) & 1) << 3)) * 2);

    for (int t = 0; t < nT; ++t) {
        if (t + 1 < nT) cp_wait1(); else cp_wait0();
        __syncthreads();

        if (t + 1 < nT) stsW((t + 1) & 1);        // buf (t+1)&1 free since sync
        if (t + 2 < nT) ldgW((t + 2) * BK);
        if (t + 2 < nT) issueA((t + 2) % 3, (t + 2) * BK);
        else            cp_commit();               // keep group counting uniform

        uint32_t sa = sbase + (t % 3) * ATB;
        uint32_t sb = sbase + WBASE + (t & 1) * ATB;

#pragma unroll
        for (int kk = 0; kk < BK; kk += 16) {
            uint32_t af[4][4];
#pragma unroll
            for (int mt = 0; mt < 4; ++mt)
                LDSM4(af[mt], sa + aOff + (uint32_t)(mt * 16 * PH + kk) * 2);
            uint32_t bf[2][4];
#pragma unroll
            for (int p = 0; p < 2; ++p)
                LDSM4(bf[p], sb + bOff + (uint32_t)(p * 16 * PH + kk) * 2);
#pragma unroll
            for (int mt = 0; mt < 4; ++mt)
#pragma unroll
                for (int nt = 0; nt < 4; ++nt)
                    mma_f16(acc[mt][nt], af[mt],
                            bf[nt >> 1][(nt & 1) * 2],
                            bf[nt >> 1][(nt & 1) * 2 + 1]);
        }
        __syncthreads();
    }

    // ---- Epilogue ----
    const int lgrp = lane >> 2;
    const int lth  = lane & 3;
#pragma unroll
    for (int nt = 0; nt < 4; ++nt) {
        int col  = bn + wn * 32 + nt * 8 + 2 * lth;
        int seg  = col / wt.segN;                 // tiles never straddle segs
        int lcol = col - seg * wt.segN;
        const float* bp = wt.b[seg];
        float bx = __ldg(bp + lcol);
        float by = __ldg(bp + lcol + 1);
#pragma unroll
        for (int mt = 0; mt < 4; ++mt) {
            int row = bm + wm * 64 + mt * 16 + lgrp;
            float v0x = acc[mt][nt][0] + bx, v0y = acc[mt][nt][1] + by;
            float v1x = acc[mt][nt][2] + bx, v1y = acc[mt][nt][3] + by;
            if (act == 1) {
                __half2 h0 = __floats2half2_rn(fmaxf(v0x, 0.f), fmaxf(v0y, 0.f));
                __half2 h1 = __floats2half2_rn(fmaxf(v1x, 0.f), fmaxf(v1y, 0.f));
                *reinterpret_cast<__half2*>(Ch + (size_t)row * N + col)       = h0;
                *reinterpret_cast<__half2*>(Ch + (size_t)(row + 8) * N + col) = h1;
            } else if (act == 0) {
                *reinterpret_cast<float2*>(Cf + (size_t)row * N + col)       = make_float2(v0x, v0y);
                *reinterpret_cast<float2*>(Cf + (size_t)(row + 8) * N + col) = make_float2(v1x, v1y);
            } else {
                if (seg == 1) {
                    v0x = (v0x > 20.f) ? v0x : log1pf(expf(v0x));
                    v0y = (v0y > 20.f) ? v0y : log1pf(expf(v0y));
                    v1x = (v1x > 20.f) ? v1x : log1pf(expf(v1x));
                    v1y = (v1y > 20.f) ? v1y : log1pf(expf(v1y));
                }
                float* dst = Cf + (size_t)seg * ((size_t)B_ * NH)
                                + (size_t)row * NH + lcol;
                *reinterpret_cast<float2*>(dst)                  = make_float2(v0x, v0y);
                *reinterpret_cast<float2*>(dst + (size_t)8 * NH) = make_float2(v1x, v1y);
            }
        }
    }
}

// ============================================================================
// Elementwise kernels
// ============================================================================
// Merged f32->f16 conversion for x and hidden (one launch).
__global__ void conv_xh_kernel(const float4* __restrict__ s0, __half2* __restrict__ d0, int n40,
                               const float4* __restrict__ s1, __half2* __restrict__ d1, int n41)
{
    int i = blockIdx.x * blockDim.x + threadIdx.x;
    if (i < n40) {
        float4 v = s0[i];
        d0[2 * i]     = __floats2half2_rn(v.x, v.y);
        d0[2 * i + 1] = __floats2half2_rn(v.z, v.w);
    } else {
        int j = i - n40;
        if (j >= n41) return;
        float4 v = s1[j];
        d1[2 * j]     = __floats2half2_rn(v.x, v.y);
        d1[2 * j + 1] = __floats2half2_rn(v.z, v.w);
    }
}

__device__ __forceinline__ float sigm(float x) { return 1.f / (1.f + expf(-x)); }

__global__ void gru_gate_kernel(const float4* __restrict__ gi,
                                const float4* __restrict__ gh,
                                const float4* __restrict__ hprev,
                                float4* __restrict__ hnew,
                                __half2* __restrict__ hh,
                                __half2* __restrict__ htanhh)
{
    int idx = blockIdx.x * blockDim.x + threadIdx.x;
    if (idx >= B_ * H_ / 4) return;
    int b  = idx >> 8;
    int jj = idx & 255;
    const float4* gib = gi + (size_t)b * (3 * H_ / 4);
    const float4* ghb = gh + (size_t)b * (3 * H_ / 4);
    float4 ir = gib[jj], iz = gib[256 + jj], in_ = gib[512 + jj];
    float4 hr = ghb[jj], hz = ghb[256 + jj], hn  = ghb[512 + jj];
    float4 hp = hprev[idx];
    float4 h;
    {
        float r = sigm(ir.x + hr.x), z = sigm(iz.x + hz.x);
        float n = tanhf(in_.x + r * hn.x);
        h.x = (1.f - z) * n + z * hp.x;
    }
    {
        float r = sigm(ir.y + hr.y), z = sigm(iz.y + hz.y);
        float n = tanhf(in_.y + r * hn.y);
        h.y = (1.f - z) * n + z * hp.y;
    }
    {
        float r = sigm(ir.z + hr.z), z = sigm(iz.z + hz.z);
        float n = tanhf(in_.z + r * hn.z);
        h.z = (1.f - z) * n + z * hp.z;
    }
    {
        float r = sigm(ir.w + hr.w), z = sigm(iz.w + hz.w);
        float n = tanhf(in_.w + r * hn.w);
        h.w = (1.f - z) * n + z * hp.w;
    }
    hnew[idx] = h;
    if (hh) {
        hh[2 * idx]     = __floats2half2_rn(h.x, h.y);
        hh[2 * idx + 1] = __floats2half2_rn(h.z, h.w);
    }
    if (htanhh) {
        htanhh[2 * idx]     = __floats2half2_rn(tanhf(h.x), tanhf(h.y));
        htanhh[2 * idx + 1] = __floats2half2_rn(tanhf(h.z), tanhf(h.w));
    }
}

__global__ void pi_softmax_kernel(float* __restrict__ pi)
{
    int idx = blockIdx.x * blockDim.x + threadIdx.x;
    if (idx >= B_ * O_) return;
    int b = idx >> 8;
    int o = idx & (O_ - 1);
    float* p = pi + (size_t)b * NH + o;
    float v0 = p[0], v1 = p[O_], v2 = p[2 * O_];
    float m = fmaxf(v0, fmaxf(v1, v2));
    float e0 = expf(v0 - m), e1 = expf(v1 - m), e2 = expf(v2 - m);
    float inv = 1.f / (e0 + e1 + e2);
    p[0] = e0 * inv; p[O_] = e1 * inv; p[2 * O_] = e2 * inv;
}

// ============================================================================
// Host
// ============================================================================
extern "C" void kernel_launch(void* const* d_in, const int* in_sizes, int n_in,
                              void* d_out, int out_size)
{
    const float* x       = (const float*)d_in[0];
    const float* hidden  = (const float*)d_in[1];
    const float* i2d_w   = (const float*)d_in[2];
    const float* i2d_b   = (const float*)d_in[3];
    const float* w_ih    = (const float*)d_in[4];
    const float* w_hh    = (const float*)d_in[5];
    const float* b_ih    = (const float*)d_in[6];
    const float* b_hh    = (const float*)d_in[7];
    const float* mu_w    = (const float*)d_in[8];
    const float* mu_b    = (const float*)d_in[9];
    const float* sigma_w = (const float*)d_in[10];
    const float* sigma_b = (const float*)d_in[11];
    const float* pi_w    = (const float*)d_in[12];
    const float* pi_b    = (const float*)d_in[13];

    float* out = (float*)d_out;
    const size_t head_sz = (size_t)B_ * NH;
    float* out_pi     = out + 2 * head_sz;
    float* out_hidden = out + 3 * head_sz;

    __half *xh, *hidh, *h1h, *h2h, *houth;
    float  *gi, *gh;
    cudaGetSymbolAddress((void**)&xh,    g_xh);
    cudaGetSymbolAddress((void**)&hidh,  g_hidh);
    cudaGetSymbolAddress((void**)&h1h,   g_h1h);
    cudaGetSymbolAddress((void**)&gi,    g_gi);
    cudaGetSymbolAddress((void**)&gh,    g_gh);
    cudaGetSymbolAddress((void**)&h2h,   g_h2h);
    cudaGetSymbolAddress((void**)&houth, g_houth);

    const size_t lw = (size_t)3 * H_ * H_;
    const size_t lb = (size_t)3 * H_;
    const size_t lh = (size_t)B_ * H_;

    static bool attr_set = false;
    if (!attr_set) {
        cudaFuncSetAttribute(gemm_f16,
                             cudaFuncAttributeMaxDynamicSharedMemorySize, SMEM_BYTES);
        attr_set = true;
    }

    auto gemm = [&](const __half* A, const float* W, const float* bias,
                    float* Cf, __half* Ch, int M, int N, int K, int act) {
        WTab wt;
        wt.w[0] = W;   wt.w[1] = W;   wt.w[2] = W;
        wt.b[0] = bias; wt.b[1] = bias; wt.b[2] = bias;
        wt.segN = N;
        dim3 grid(N / BN, M / BM);
        gemm_f16<<<grid, 256, SMEM_BYTES>>>(A, wt, nullptr, Cf, Ch, M, N, K, act);
    };

    const int gateGrid = (B_ * H_ / 4) / 256;
    const int smGrid   = (B_ * O_) / 256;

    // 1) merged conversion: x -> xh, hidden -> hidh (one launch)
    {
        int n40 = B_ * IN_ / 4;
        int n41 = L_ * B_ * H_ / 4;
        int total = n40 + n41;
        conv_xh_kernel<<<(total + 255) / 256, 256>>>(
            (const float4*)x, (__half2*)xh, n40,
            (const float4*)hidden, (__half2*)hidh, n41);
    }

    // 2) i2d: h1 = relu(x @ i2d_w^T + b) -> half
    gemm(xh, i2d_w, i2d_b, nullptr, h1h, B_, H_, IN_, 1);

    // 3,4,5) GRU layer 0
    gemm(hidh,      w_hh,      b_hh,      gh, nullptr, B_, 3 * H_, H_, 0);
    gemm(h1h,       w_ih,      b_ih,      gi, nullptr, B_, 3 * H_, H_, 0);
    gru_gate_kernel<<<gateGrid, 256>>>((const float4*)gi, (const float4*)gh,
                                       (const float4*)hidden,
                                       (float4*)out_hidden, (__half2*)h2h, nullptr);

    // 6,7,8) GRU layer 1  (launch #6 = gh1 GEMM -> ncu capture target)
    gemm(hidh + lh, w_hh + lw, b_hh + lb, gh, nullptr, B_, 3 * H_, H_, 0);
    gemm(h2h,       w_ih + lw, b_ih + lb, gi, nullptr, B_, 3 * H_, H_, 0);
    gru_gate_kernel<<<gateGrid, 256>>>((const float4*)gi, (const float4*)gh,
                                       (const float4*)(hidden + lh),
                                       (float4*)(out_hidden + lh), nullptr,
                                       (__half2*)houth);

    // 9) MDN heads: one fused GEMM (mu | sigma | pi), N = 2304, segmented W
    {
        WTab wt;
        wt.w[0] = mu_w;  wt.w[1] = sigma_w;  wt.w[2] = pi_w;
        wt.b[0] = mu_b;  wt.b[1] = sigma_b;  wt.b[2] = pi_b;
        wt.segN = NH;
        dim3 grid(NHEADS3 / BN, B_ / BM);
        gemm_f16<<<grid, 256, SMEM_BYTES>>>(houth, wt, nullptr, out, nullptr,
                                            B_, NHEADS3, H_, 2);
    }

    // 10) pi softmax
    pi_softmax_kernel<<<smGrid, 256>>>(out_pi);
}

// round 6
// speedup vs baseline: 1.1036x; 1.1036x over previous
#include <cuda_runtime.h>
#include <cuda_fp16.h>
#include <math.h>
#include <stdint.h>

// ============================================================================
// Problem constants
// ============================================================================
#define B_  4096
#define IN_ 512
#define H_  1024
#define O_  256
#define L_  2
#define G_  3
#define NH  (G_ * O_)        // 768 per head
#define NHEADS3 (3 * NH)     // 2304 fused head columns

// ============================================================================
// GEMM tiling (mma.sync m16n8k16 f16, ldmatrix feeds, all-half operands)
// ============================================================================
#define BM 128
#define BN 128
#define BK 32
#define PH 40                           // smem pitch in halves (80 B rows)
#define ATB (BM * PH * 2)               // 10240 B per operand tile
#define STG_BYTES (2 * ATB)             // 20480 (A + W per stage)
#define NSTG 4
#define SMEM_BYTES (NSTG * STG_BYTES)   // 81920

// ============================================================================
// Scratch (device globals)
// ============================================================================
static __device__ __align__(256) __half g_xh    [(size_t)B_ * IN_];
static __device__ __align__(256) __half g_hidh  [(size_t)L_ * B_ * H_];
static __device__ __align__(256) __half g_i2dwh [(size_t)H_ * IN_];
static __device__ __align__(256) __half g_wihh  [(size_t)L_ * 3 * H_ * H_];
static __device__ __align__(256) __half g_whhh  [(size_t)L_ * 3 * H_ * H_];
static __device__ __align__(256) __half g_headwh[(size_t)NHEADS3 * H_];
static __device__ __align__(256) __half g_h1h   [(size_t)B_ * H_];
static __device__ __align__(256) float  g_gi    [(size_t)B_ * 3 * H_];
static __device__ __align__(256) float  g_gh    [(size_t)B_ * 3 * H_];
static __device__ __align__(256) __half g_h2h   [(size_t)B_ * H_];
static __device__ __align__(256) __half g_houth [(size_t)B_ * H_];

// ============================================================================
// PTX helpers
// ============================================================================
__device__ __forceinline__ void cp_async16(uint32_t saddr, const void* gptr) {
    asm volatile("cp.async.cg.shared.global [%0], [%1], 16;"
                 :: "r"(saddr), "l"(gptr) : "memory");
}
__device__ __forceinline__ void cp_commit() {
    asm volatile("cp.async.commit_group;" ::: "memory");
}
__device__ __forceinline__ void cp_wait2() {
    asm volatile("cp.async.wait_group 2;" ::: "memory");
}
__device__ __forceinline__ void cp_wait1() {
    asm volatile("cp.async.wait_group 1;" ::: "memory");
}
__device__ __forceinline__ void cp_wait0() {
    asm volatile("cp.async.wait_group 0;" ::: "memory");
}

#define LDSM4(r, a) \
    asm volatile("ldmatrix.sync.aligned.m8n8.x4.shared.b16 {%0,%1,%2,%3}, [%4];" \
        : "=r"((r)[0]), "=r"((r)[1]), "=r"((r)[2]), "=r"((r)[3]) : "r"(a))

__device__ __forceinline__ void mma_f16(float c[4], const uint32_t a[4],
                                        uint32_t b0, uint32_t b1) {
    asm volatile(
        "mma.sync.aligned.m16n8k16.row.col.f32.f16.f16.f32 "
        "{%0,%1,%2,%3}, {%4,%5,%6,%7}, {%8,%9}, {%0,%1,%2,%3};"
        : "+f"(c[0]), "+f"(c[1]), "+f"(c[2]), "+f"(c[3])
        : "r"(a[0]), "r"(a[1]), "r"(a[2]), "r"(a[3]), "r"(b0), "r"(b1));
}

__device__ __forceinline__ float tanha(float x) {
    float y;
    asm("tanh.approx.f32 %0, %1;" : "=f"(y) : "f"(x));
    return y;
}
__device__ __forceinline__ float sigma_f(float x) {     // sigmoid via HW tanh
    return fmaf(0.5f, tanha(0.5f * x), 0.5f);
}

// ============================================================================
// GEMM: C[M,N] = A[M,K] @ W[N,K]^T + bias[N]
//   A, W: __half row-major (K contiguous). fp32 accumulate.
//   act 0: fp32 out to Cf (stride N)
//   act 1: relu -> __half out to Ch (stride N)
//   act 2: fused-heads: seg = col/segN (segN=768), softplus on seg 1,
//          out = Cf + seg*M*segN + row*segN + (col - seg*segN)
//   Bias via 3-pointer table (b0,b1,b2) selected by seg (all same if segN==N).
// ============================================================================
__global__ __launch_bounds__(256, 2)
void gemm_f16(const __half* __restrict__ A, const __half* __restrict__ W,
              const float* __restrict__ b0, const float* __restrict__ b1,
              const float* __restrict__ b2, int segN,
              float* __restrict__ Cf, __half* __restrict__ Ch,
              int M, int N, int K, int act)
{
    extern __shared__ char smem_raw[];
    const uint32_t sbase = (uint32_t)__cvta_generic_to_shared(smem_raw);

    const int tid  = threadIdx.x;
    const int lane = tid & 31;
    const int wid  = tid >> 5;
    const int wm   = wid & 1;            // 2 warps along M (64 rows)
    const int wn   = wid >> 1;           // 4 warps along N (32 cols)
    const int bm   = blockIdx.y * BM;
    const int bn   = blockIdx.x * BN;

    float acc[4][4][4];
#pragma unroll
    for (int i = 0; i < 4; ++i)
#pragma unroll
        for (int j = 0; j < 4; ++j)
#pragma unroll
            for (int q = 0; q < 4; ++q) acc[i][j][q] = 0.f;

    // cp.async: 2 x 16B per thread for A and for W per stage
    auto issue = [&](int stg, int kt) {
        uint32_t sa = sbase + stg * STG_BYTES;
        uint32_t sb = sa + ATB;
#pragma unroll
        for (int i = 0; i < 2; ++i) {
            int idx = tid + i * 256;
            int row = idx >> 2;
            int c8  = (idx & 3) << 3;
            uint32_t doff = (uint32_t)(row * PH + c8) * 2;
            cp_async16(sa + doff, A + (size_t)(bm + row) * K + kt + c8);
            cp_async16(sb + doff, W + (size_t)(bn + row) * K + kt + c8);
        }
        cp_commit();
    };

    const int nT = K / BK;               // >= 16 for all our shapes
    issue(0, 0);
    issue(1, BK);
    issue(2, 2 * BK);

    // ldmatrix lane addressing (pitch PH halves)
    const uint32_t aOff = (uint32_t)(((wm * 64 + (lane & 15)) * PH +
                                      ((lane >> 4) << 3)) * 2);
    const uint32_t bOff = (uint32_t)(((wn * 32 + ((lane >> 4) << 3) + (lane & 7)) * PH +
                                      (((lane >> 3) & 1) << 3)) * 2);

    for (int t = 0; t < nT; ++t) {
        int rem = nT - 1 - t;            // groups still outstanding beyond t
        if (rem >= 2)      cp_wait2();
        else if (rem == 1) cp_wait1();
        else               cp_wait0();
        __syncthreads();                 // one barrier per K-tile

        if (t + 3 < nT) issue((t + 3) & (NSTG - 1), (t + 3) * BK);

        uint32_t sa = sbase + (t & (NSTG - 1)) * STG_BYTES;
        uint32_t sb = sa + ATB;

#pragma unroll
        for (int kk = 0; kk < BK; kk += 16) {
            uint32_t af[4][4];
#pragma unroll
            for (int mt = 0; mt < 4; ++mt)
                LDSM4(af[mt], sa + aOff + (uint32_t)(mt * 16 * PH + kk) * 2);
            uint32_t bf[2][4];
#pragma unroll
            for (int p = 0; p < 2; ++p)
                LDSM4(bf[p], sb + bOff + (uint32_t)(p * 16 * PH + kk) * 2);
#pragma unroll
            for (int mt = 0; mt < 4; ++mt)
#pragma unroll
                for (int nt = 0; nt < 4; ++nt)
                    mma_f16(acc[mt][nt], af[mt],
                            bf[nt >> 1][(nt & 1) * 2],
                            bf[nt >> 1][(nt & 1) * 2 + 1]);
        }
    }

    // ---- Epilogue ----
    const int lgrp = lane >> 2;
    const int lth  = lane & 3;
#pragma unroll
    for (int nt = 0; nt < 4; ++nt) {
        int col  = bn + wn * 32 + nt * 8 + 2 * lth;
        int seg  = col / segN;           // 128-tiles never straddle segments
        int lcol = col - seg * segN;
        const float* bp = (seg == 0) ? b0 : (seg == 1) ? b1 : b2;
        float bx = __ldg(bp + lcol);
        float by = __ldg(bp + lcol + 1);
#pragma unroll
        for (int mt = 0; mt < 4; ++mt) {
            int row = bm + wm * 64 + mt * 16 + lgrp;
            float v0x = acc[mt][nt][0] + bx, v0y = acc[mt][nt][1] + by;
            float v1x = acc[mt][nt][2] + bx, v1y = acc[mt][nt][3] + by;
            if (act == 1) {
                __half2 h0 = __floats2half2_rn(fmaxf(v0x, 0.f), fmaxf(v0y, 0.f));
                __half2 h1 = __floats2half2_rn(fmaxf(v1x, 0.f), fmaxf(v1y, 0.f));
                *reinterpret_cast<__half2*>(Ch + (size_t)row * N + col)       = h0;
                *reinterpret_cast<__half2*>(Ch + (size_t)(row + 8) * N + col) = h1;
            } else if (act == 0) {
                *reinterpret_cast<float2*>(Cf + (size_t)row * N + col)       = make_float2(v0x, v0y);
                *reinterpret_cast<float2*>(Cf + (size_t)(row + 8) * N + col) = make_float2(v1x, v1y);
            } else {
                if (seg == 1) {          // softplus for sigma head
                    v0x = (v0x > 20.f) ? v0x : log1pf(__expf(v0x));
                    v0y = (v0y > 20.f) ? v0y : log1pf(__expf(v0y));
                    v1x = (v1x > 20.f) ? v1x : log1pf(__expf(v1x));
                    v1y = (v1y > 20.f) ? v1y : log1pf(__expf(v1y));
                }
                float* dst = Cf + (size_t)seg * ((size_t)B_ * NH)
                                + (size_t)row * NH + lcol;
                *reinterpret_cast<float2*>(dst)                  = make_float2(v0x, v0y);
                *reinterpret_cast<float2*>(dst + (size_t)8 * NH) = make_float2(v1x, v1y);
            }
        }
    }
}

// ============================================================================
// Merged f32 -> f16 conversion: all 8 tensors in ONE launch
// ============================================================================
struct ConvArgs {
    const float4* src[8];
    __half2*      dst[8];
    int           end[8];    // exclusive prefix ends (in float4 units)
};

__global__ void conv_all_kernel(const __grid_constant__ ConvArgs a)
{
    int i = blockIdx.x * blockDim.x + threadIdx.x;
    int prev = 0;
#pragma unroll
    for (int j = 0; j < 8; ++j) {
        if (i < a.end[j]) {
            int k = i - prev;
            float4 v = a.src[j][k];
            a.dst[j][2 * k]     = __floats2half2_rn(v.x, v.y);
            a.dst[j][2 * k + 1] = __floats2half2_rn(v.z, v.w);
            return;
        }
        prev = a.end[j];
    }
}

// ============================================================================
// GRU gate fusion (HW tanh.approx)
// ============================================================================
__global__ void gru_gate_kernel(const float4* __restrict__ gi,
                                const float4* __restrict__ gh,
                                const float4* __restrict__ hprev,
                                float4* __restrict__ hnew,
                                __half2* __restrict__ hh,
                                __half2* __restrict__ htanhh)
{
    int idx = blockIdx.x * blockDim.x + threadIdx.x;
    if (idx >= B_ * H_ / 4) return;
    int b  = idx >> 8;
    int jj = idx & 255;
    const float4* gib = gi + (size_t)b * (3 * H_ / 4);
    const float4* ghb = gh + (size_t)b * (3 * H_ / 4);
    float4 ir = gib[jj], iz = gib[256 + jj], in_ = gib[512 + jj];
    float4 hr = ghb[jj], hz = ghb[256 + jj], hn  = ghb[512 + jj];
    float4 hp = hprev[idx];
    float4 h;
    {
        float r = sigma_f(ir.x + hr.x), z = sigma_f(iz.x + hz.x);
        float n = tanha(fmaf(r, hn.x, in_.x));
        h.x = fmaf(z, hp.x - n, n);
    }
    {
        float r = sigma_f(ir.y + hr.y), z = sigma_f(iz.y + hz.y);
        float n = tanha(fmaf(r, hn.y, in_.y));
        h.y = fmaf(z, hp.y - n, n);
    }
    {
        float r = sigma_f(ir.z + hr.z), z = sigma_f(iz.z + hz.z);
        float n = tanha(fmaf(r, hn.z, in_.z));
        h.z = fmaf(z, hp.z - n, n);
    }
    {
        float r = sigma_f(ir.w + hr.w), z = sigma_f(iz.w + hz.w);
        float n = tanha(fmaf(r, hn.w, in_.w));
        h.w = fmaf(z, hp.w - n, n);
    }
    hnew[idx] = h;
    if (hh) {
        hh[2 * idx]     = __floats2half2_rn(h.x, h.y);
        hh[2 * idx + 1] = __floats2half2_rn(h.z, h.w);
    }
    if (htanhh) {
        htanhh[2 * idx]     = __floats2half2_rn(tanha(h.x), tanha(h.y));
        htanhh[2 * idx + 1] = __floats2half2_rn(tanha(h.z), tanha(h.w));
    }
}

__global__ void pi_softmax_kernel(float* __restrict__ pi)
{
    int idx = blockIdx.x * blockDim.x + threadIdx.x;
    if (idx >= B_ * O_) return;
    int b = idx >> 8;
    int o = idx & (O_ - 1);
    float* p = pi + (size_t)b * NH + o;
    float v0 = p[0], v1 = p[O_], v2 = p[2 * O_];
    float m = fmaxf(v0, fmaxf(v1, v2));
    float e0 = __expf(v0 - m), e1 = __expf(v1 - m), e2 = __expf(v2 - m);
    float inv = 1.f / (e0 + e1 + e2);
    p[0] = e0 * inv; p[O_] = e1 * inv; p[2 * O_] = e2 * inv;
}

// ============================================================================
// Host
// ============================================================================
extern "C" void kernel_launch(void* const* d_in, const int* in_sizes, int n_in,
                              void* d_out, int out_size)
{
    const float* x       = (const float*)d_in[0];
    const float* hidden  = (const float*)d_in[1];
    const float* i2d_w   = (const float*)d_in[2];
    const float* i2d_b   = (const float*)d_in[3];
    const float* w_ih    = (const float*)d_in[4];
    const float* w_hh    = (const float*)d_in[5];
    const float* b_ih    = (const float*)d_in[6];
    const float* b_hh    = (const float*)d_in[7];
    const float* mu_w    = (const float*)d_in[8];
    const float* mu_b    = (const float*)d_in[9];
    const float* sigma_w = (const float*)d_in[10];
    const float* sigma_b = (const float*)d_in[11];
    const float* pi_w    = (const float*)d_in[12];
    const float* pi_b    = (const float*)d_in[13];

    float* out = (float*)d_out;
    const size_t head_sz = (size_t)B_ * NH;
    float* out_pi     = out + 2 * head_sz;
    float* out_hidden = out + 3 * head_sz;

    __half *xh, *hidh, *i2dwh, *wihh, *whhh, *headwh, *h1h, *h2h, *houth;
    float  *gi, *gh;
    cudaGetSymbolAddress((void**)&xh,     g_xh);
    cudaGetSymbolAddress((void**)&hidh,   g_hidh);
    cudaGetSymbolAddress((void**)&i2dwh,  g_i2dwh);
    cudaGetSymbolAddress((void**)&wihh,   g_wihh);
    cudaGetSymbolAddress((void**)&whhh,   g_whhh);
    cudaGetSymbolAddress((void**)&headwh, g_headwh);
    cudaGetSymbolAddress((void**)&h1h,    g_h1h);
    cudaGetSymbolAddress((void**)&gi,     g_gi);
    cudaGetSymbolAddress((void**)&gh,     g_gh);
    cudaGetSymbolAddress((void**)&h2h,    g_h2h);
    cudaGetSymbolAddress((void**)&houth,  g_houth);

    const size_t lw = (size_t)3 * H_ * H_;
    const size_t lb = (size_t)3 * H_;
    const size_t lh = (size_t)B_ * H_;

    static bool attr_set = false;
    if (!attr_set) {
        cudaFuncSetAttribute(gemm_f16,
                             cudaFuncAttributeMaxDynamicSharedMemorySize, SMEM_BYTES);
        attr_set = true;
    }

    auto gemm = [&](const __half* A, const __half* W, const float* bias,
                    float* Cf, __half* Ch, int M, int N, int K, int act) {
        dim3 grid(N / BN, M / BM);
        gemm_f16<<<grid, 256, SMEM_BYTES>>>(A, W, bias, bias, bias, N,
                                            Cf, Ch, M, N, K, act);
    };

    const int gateGrid = (B_ * H_ / 4) / 256;
    const int smGrid   = (B_ * O_) / 256;

    // 1) ONE merged conversion launch: x, hidden, all weights -> half
    {
        ConvArgs ca;
        int e = 0, j = 0;
        auto add = [&](const float* s, __half* d, size_t n) {
            ca.src[j] = (const float4*)s;
            ca.dst[j] = (__half2*)d;
            e += (int)(n / 4);
            ca.end[j] = e;
            ++j;
        };
        add(x,       xh,     (size_t)B_ * IN_);
        add(hidden,  hidh,   (size_t)L_ * B_ * H_);
        add(i2d_w,   i2dwh,  (size_t)H_ * IN_);
        add(w_ih,    wihh,   (size_t)L_ * lw);
        add(w_hh,    whhh,   (size_t)L_ * lw);
        add(mu_w,    headwh,                       (size_t)NH * H_);
        add(sigma_w, headwh + (size_t)NH * H_,     (size_t)NH * H_);
        add(pi_w,    headwh + (size_t)2 * NH * H_, (size_t)NH * H_);
        conv_all_kernel<<<(e + 255) / 256, 256>>>(ca);
    }

    // 2) i2d: h1 = relu(x @ i2d_w^T + b) -> half
    gemm(xh, i2dwh, i2d_b, nullptr, h1h, B_, H_, IN_, 1);

    // 3,4,5) GRU layer 0
    gemm(hidh,      whhh,      b_hh,      gh, nullptr, B_, 3 * H_, H_, 0);
    gemm(h1h,       wihh,      b_ih,      gi, nullptr, B_, 3 * H_, H_, 0);
    gru_gate_kernel<<<gateGrid, 256>>>((const float4*)gi, (const float4*)gh,
                                       (const float4*)hidden,
                                       (float4*)out_hidden, (__half2*)h2h, nullptr);

    // 6,7,8) GRU layer 1  (launch #6 = gh1 GEMM -> ncu capture target)
    gemm(hidh + lh, whhh + lw, b_hh + lb, gh, nullptr, B_, 3 * H_, H_, 0);
    gemm(h2h,       wihh + lw, b_ih + lb, gi, nullptr, B_, 3 * H_, H_, 0);
    gru_gate_kernel<<<gateGrid, 256>>>((const float4*)gi, (const float4*)gh,
                                       (const float4*)(hidden + lh),
                                       (float4*)(out_hidden + lh), nullptr,
                                       (__half2*)houth);

    // 9) MDN heads: one fused GEMM (mu | sigma | pi), N = 2304
    {
        dim3 grid(NHEADS3 / BN, B_ / BM);
        gemm_f16<<<grid, 256, SMEM_BYTES>>>(houth, headwh,
                                            mu_b, sigma_b, pi_b, NH,
                                            out, nullptr, B_, NHEADS3, H_, 2);
    }

    // 10) pi softmax
    pi_softmax_kernel<<<smGrid, 256>>>(out_pi);
}

// round 7
// speedup vs baseline: 1.1668x; 1.0573x over previous
#include <cuda_runtime.h>
#include <cuda_fp16.h>
#include <math.h>
#include <stdint.h>

// ============================================================================
// Problem constants
// ============================================================================
#define B_  4096
#define IN_ 512
#define H_  1024
#define O_  256
#define L_  2
#define G_  3
#define NH  (G_ * O_)        // 768 per head
#define NHEADS3 (3 * NH)     // 2304 fused head columns

// ============================================================================
// GEMM tiling (mma.sync m16n8k16 f16, ldmatrix feeds, all-half operands)
// ============================================================================
#define BM 128
#define BN 128
#define BK 32
#define PH 40                           // smem pitch in halves (80 B rows)
#define ATB (BM * PH * 2)               // 10240 B per operand tile
#define STG_BYTES (2 * ATB)             // 20480 (A + W per stage)
#define NSTG 4
#define SMEM_BYTES (NSTG * STG_BYTES)   // 81920

// ============================================================================
// Scratch (device globals)
// ============================================================================
static __device__ __align__(256) __half g_xh    [(size_t)B_ * IN_];
static __device__ __align__(256) __half g_hidh  [(size_t)L_ * B_ * H_];
static __device__ __align__(256) __half g_i2dwh [(size_t)H_ * IN_];
static __device__ __align__(256) __half g_wihh  [(size_t)L_ * 3 * H_ * H_];
static __device__ __align__(256) __half g_whhh  [(size_t)L_ * 3 * H_ * H_];
static __device__ __align__(256) __half g_headwh[(size_t)NHEADS3 * H_];
static __device__ __align__(256) __half g_h1h   [(size_t)B_ * H_];
static __device__ __align__(256) float  g_gi    [(size_t)B_ * 3 * H_];
static __device__ __align__(256) float  g_gh    [(size_t)B_ * 3 * H_];
static __device__ __align__(256) __half g_h2h   [(size_t)B_ * H_];
static __device__ __align__(256) __half g_houth [(size_t)B_ * H_];

// ============================================================================
// PTX helpers
// ============================================================================
__device__ __forceinline__ void cp_async16(uint32_t saddr, const void* gptr) {
    asm volatile("cp.async.cg.shared.global [%0], [%1], 16;"
                 :: "r"(saddr), "l"(gptr) : "memory");
}
__device__ __forceinline__ void cp_commit() {
    asm volatile("cp.async.commit_group;" ::: "memory");
}
__device__ __forceinline__ void cp_wait2() {
    asm volatile("cp.async.wait_group 2;" ::: "memory");
}
__device__ __forceinline__ void cp_wait1() {
    asm volatile("cp.async.wait_group 1;" ::: "memory");
}

#define LDSM4(r, a) \
    asm volatile("ldmatrix.sync.aligned.m8n8.x4.shared.b16 {%0,%1,%2,%3}, [%4];" \
        : "=r"((r)[0]), "=r"((r)[1]), "=r"((r)[2]), "=r"((r)[3]) : "r"(a))

__device__ __forceinline__ void mma_f16(float c[4], const uint32_t a[4],
                                        uint32_t b0, uint32_t b1) {
    asm volatile(
        "mma.sync.aligned.m16n8k16.row.col.f32.f16.f16.f32 "
        "{%0,%1,%2,%3}, {%4,%5,%6,%7}, {%8,%9}, {%0,%1,%2,%3};"
        : "+f"(c[0]), "+f"(c[1]), "+f"(c[2]), "+f"(c[3])
        : "r"(a[0]), "r"(a[1]), "r"(a[2]), "r"(a[3]), "r"(b0), "r"(b1));
}

__device__ __forceinline__ float tanha(float x) {
    float y;
    asm("tanh.approx.f32 %0, %1;" : "=f"(y) : "f"(x));
    return y;
}
__device__ __forceinline__ float sigma_f(float x) {     // sigmoid via HW tanh
    return fmaf(0.5f, tanha(0.5f * x), 0.5f);
}

// ============================================================================
// GEMM: C[M,N] = A[M,K] @ W[N,K]^T + bias[N]
//   A, W: __half row-major (K contiguous). fp32 accumulate.
//   act 0: fp32 out to Cf (stride N)
//   act 1: relu -> __half out to Ch (stride N)
//   act 2: fused-heads: seg = col/segN (segN=768), softplus on seg 1,
//          out = Cf + seg*M*segN + row*segN + (col - seg*segN)
//   Fragment software pipeline at k=16 half-tile granularity: ldmatrix for
//   half g+1 issues before MMAs for half g (LDS latency hidden).
// ============================================================================
__global__ __launch_bounds__(256, 2)
void gemm_f16(const __half* __restrict__ A, const __half* __restrict__ W,
              const float* __restrict__ b0, const float* __restrict__ b1,
              const float* __restrict__ b2, int segN,
              float* __restrict__ Cf, __half* __restrict__ Ch,
              int M, int N, int K, int act)
{
    extern __shared__ char smem_raw[];
    const uint32_t sbase = (uint32_t)__cvta_generic_to_shared(smem_raw);

    const int tid  = threadIdx.x;
    const int lane = tid & 31;
    const int wid  = tid >> 5;
    const int wm   = wid & 1;            // 2 warps along M (64 rows)
    const int wn   = wid >> 1;           // 4 warps along N (32 cols)
    const int bm   = blockIdx.y * BM;
    const int bn   = blockIdx.x * BN;

    float acc[4][4][4];
#pragma unroll
    for (int i = 0; i < 4; ++i)
#pragma unroll
        for (int j = 0; j < 4; ++j)
#pragma unroll
            for (int q = 0; q < 4; ++q) acc[i][j][q] = 0.f;

    // cp.async: 2 x 16B per thread for A and for W per stage
    auto issue = [&](int stg, int kt) {
        uint32_t sa = sbase + stg * STG_BYTES;
        uint32_t sb = sa + ATB;
#pragma unroll
        for (int i = 0; i < 2; ++i) {
            int idx = tid + i * 256;
            int row = idx >> 2;
            int c8  = (idx & 3) << 3;
            uint32_t doff = (uint32_t)(row * PH + c8) * 2;
            cp_async16(sa + doff, A + (size_t)(bm + row) * K + kt + c8);
            cp_async16(sb + doff, W + (size_t)(bn + row) * K + kt + c8);
        }
        cp_commit();
    };

    const int nT = K / BK;               // 16..32 for our shapes
    issue(0, 0);
    issue(1, BK);
    issue(2, 2 * BK);

    // ldmatrix lane addressing (pitch PH halves)
    const uint32_t aOff = (uint32_t)(((wm * 64 + (lane & 15)) * PH +
                                      ((lane >> 4) << 3)) * 2);
    const uint32_t bOff = (uint32_t)(((wn * 32 + ((lane >> 4) << 3) + (lane & 7)) * PH +
                                      (((lane >> 3) & 1) << 3)) * 2);

    // Double-buffered fragments (half-tile granularity)
    uint32_t afb[2][4][4];
    uint32_t bfb[2][2][4];

    // ldsm for half-tile: stage s, kk in {0,16}, into buffer bsel
    auto ldsm_half = [&](int s, int kk, int bsel) {
        uint32_t sa = sbase + s * STG_BYTES;
        uint32_t sb = sa + ATB;
#pragma unroll
        for (int mt = 0; mt < 4; ++mt)
            LDSM4(afb[bsel][mt], sa + aOff + (uint32_t)(mt * 16 * PH + kk) * 2);
#pragma unroll
        for (int p = 0; p < 2; ++p)
            LDSM4(bfb[bsel][p], sb + bOff + (uint32_t)(p * 16 * PH + kk) * 2);
    };
    auto mma_half = [&](int bsel) {
#pragma unroll
        for (int mt = 0; mt < 4; ++mt)
#pragma unroll
            for (int nt = 0; nt < 4; ++nt)
                mma_f16(acc[mt][nt], afb[bsel][mt],
                        bfb[bsel][nt >> 1][(nt & 1) * 2],
                        bfb[bsel][nt >> 1][(nt & 1) * 2 + 1]);
    };

    // Prologue: stage 0 ready, preload half 0 into buf 0
    cp_wait2();
    __syncthreads();
    ldsm_half(0, 0, 0);

    for (int t = 0; t < nT; ++t) {
        const int s = t & (NSTG - 1);
        // half A (g = 2t): preload half 2t+1 (same stage, kk=16), then MMA buf0
        ldsm_half(s, 16, 1);
        mma_half(0);
        // half B (g = 2t+1): boundary to next tile
        if (t + 1 < nT) {
            cp_wait1();
            __syncthreads();
            if (t + 3 < nT) issue((t + 3) & (NSTG - 1), (t + 3) * BK);
            ldsm_half((t + 1) & (NSTG - 1), 0, 0);
        }
        mma_half(1);
    }

    // ---- Epilogue ----
    const int lgrp = lane >> 2;
    const int lth  = lane & 3;
#pragma unroll
    for (int nt = 0; nt < 4; ++nt) {
        int col  = bn + wn * 32 + nt * 8 + 2 * lth;
        int seg  = col / segN;           // 128-tiles never straddle segments
        int lcol = col - seg * segN;
        const float* bp = (seg == 0) ? b0 : (seg == 1) ? b1 : b2;
        float bx = __ldg(bp + lcol);
        float by = __ldg(bp + lcol + 1);
#pragma unroll
        for (int mt = 0; mt < 4; ++mt) {
            int row = bm + wm * 64 + mt * 16 + lgrp;
            float v0x = acc[mt][nt][0] + bx, v0y = acc[mt][nt][1] + by;
            float v1x = acc[mt][nt][2] + bx, v1y = acc[mt][nt][3] + by;
            if (act == 1) {
                __half2 h0 = __floats2half2_rn(fmaxf(v0x, 0.f), fmaxf(v0y, 0.f));
                __half2 h1 = __floats2half2_rn(fmaxf(v1x, 0.f), fmaxf(v1y, 0.f));
                *reinterpret_cast<__half2*>(Ch + (size_t)row * N + col)       = h0;
                *reinterpret_cast<__half2*>(Ch + (size_t)(row + 8) * N + col) = h1;
            } else if (act == 0) {
                *reinterpret_cast<float2*>(Cf + (size_t)row * N + col)       = make_float2(v0x, v0y);
                *reinterpret_cast<float2*>(Cf + (size_t)(row + 8) * N + col) = make_float2(v1x, v1y);
            } else {
                if (seg == 1) {          // softplus for sigma head
                    v0x = (v0x > 20.f) ? v0x : log1pf(__expf(v0x));
                    v0y = (v0y > 20.f) ? v0y : log1pf(__expf(v0y));
                    v1x = (v1x > 20.f) ? v1x : log1pf(__expf(v1x));
                    v1y = (v1y > 20.f) ? v1y : log1pf(__expf(v1y));
                }
                float* dst = Cf + (size_t)seg * ((size_t)B_ * NH)
                                + (size_t)row * NH + lcol;
                *reinterpret_cast<float2*>(dst)                  = make_float2(v0x, v0y);
                *reinterpret_cast<float2*>(dst + (size_t)8 * NH) = make_float2(v1x, v1y);
            }
        }
    }
}

// ============================================================================
// Merged f32 -> f16 conversion: all 8 tensors in ONE launch
// ============================================================================
struct ConvArgs {
    const float4* src[8];
    __half2*      dst[8];
    int           end[8];    // exclusive prefix ends (in float4 units)
};

__global__ void conv_all_kernel(const __grid_constant__ ConvArgs a)
{
    int i = blockIdx.x * blockDim.x + threadIdx.x;
    int prev = 0;
#pragma unroll
    for (int j = 0; j < 8; ++j) {
        if (i < a.end[j]) {
            int k = i - prev;
            float4 v = a.src[j][k];
            a.dst[j][2 * k]     = __floats2half2_rn(v.x, v.y);
            a.dst[j][2 * k + 1] = __floats2half2_rn(v.z, v.w);
            return;
        }
        prev = a.end[j];
    }
}

// ============================================================================
// GRU gate fusion (HW tanh.approx)
// ============================================================================
__global__ void gru_gate_kernel(const float4* __restrict__ gi,
                                const float4* __restrict__ gh,
                                const float4* __restrict__ hprev,
                                float4* __restrict__ hnew,
                                __half2* __restrict__ hh,
                                __half2* __restrict__ htanhh)
{
    int idx = blockIdx.x * blockDim.x + threadIdx.x;
    if (idx >= B_ * H_ / 4) return;
    int b  = idx >> 8;
    int jj = idx & 255;
    const float4* gib = gi + (size_t)b * (3 * H_ / 4);
    const float4* ghb = gh + (size_t)b * (3 * H_ / 4);
    float4 ir = gib[jj], iz = gib[256 + jj], in_ = gib[512 + jj];
    float4 hr = ghb[jj], hz = ghb[256 + jj], hn  = ghb[512 + jj];
    float4 hp = hprev[idx];
    float4 h;
    {
        float r = sigma_f(ir.x + hr.x), z = sigma_f(iz.x + hz.x);
        float n = tanha(fmaf(r, hn.x, in_.x));
        h.x = fmaf(z, hp.x - n, n);
    }
    {
        float r = sigma_f(ir.y + hr.y), z = sigma_f(iz.y + hz.y);
        float n = tanha(fmaf(r, hn.y, in_.y));
        h.y = fmaf(z, hp.y - n, n);
    }
    {
        float r = sigma_f(ir.z + hr.z), z = sigma_f(iz.z + hz.z);
        float n = tanha(fmaf(r, hn.z, in_.z));
        h.z = fmaf(z, hp.z - n, n);
    }
    {
        float r = sigma_f(ir.w + hr.w), z = sigma_f(iz.w + hz.w);
        float n = tanha(fmaf(r, hn.w, in_.w));
        h.w = fmaf(z, hp.w - n, n);
    }
    hnew[idx] = h;
    if (hh) {
        hh[2 * idx]     = __floats2half2_rn(h.x, h.y);
        hh[2 * idx + 1] = __floats2half2_rn(h.z, h.w);
    }
    if (htanhh) {
        htanhh[2 * idx]     = __floats2half2_rn(tanha(h.x), tanha(h.y));
        htanhh[2 * idx + 1] = __floats2half2_rn(tanha(h.z), tanha(h.w));
    }
}

__global__ void pi_softmax_kernel(float* __restrict__ pi)
{
    int idx = blockIdx.x * blockDim.x + threadIdx.x;
    if (idx >= B_ * O_) return;
    int b = idx >> 8;
    int o = idx & (O_ - 1);
    float* p = pi + (size_t)b * NH + o;
    float v0 = p[0], v1 = p[O_], v2 = p[2 * O_];
    float m = fmaxf(v0, fmaxf(v1, v2));
    float e0 = __expf(v0 - m), e1 = __expf(v1 - m), e2 = __expf(v2 - m);
    float inv = 1.f / (e0 + e1 + e2);
    p[0] = e0 * inv; p[O_] = e1 * inv; p[2 * O_] = e2 * inv;
}

// ============================================================================
// Host
// ============================================================================
extern "C" void kernel_launch(void* const* d_in, const int* in_sizes, int n_in,
                              void* d_out, int out_size)
{
    const float* x       = (const float*)d_in[0];
    const float* hidden  = (const float*)d_in[1];
    const float* i2d_w   = (const float*)d_in[2];
    const float* i2d_b   = (const float*)d_in[3];
    const float* w_ih    = (const float*)d_in[4];
    const float* w_hh    = (const float*)d_in[5];
    const float* b_ih    = (const float*)d_in[6];
    const float* b_hh    = (const float*)d_in[7];
    const float* mu_w    = (const float*)d_in[8];
    const float* mu_b    = (const float*)d_in[9];
    const float* sigma_w = (const float*)d_in[10];
    const float* sigma_b = (const float*)d_in[11];
    const float* pi_w    = (const float*)d_in[12];
    const float* pi_b    = (const float*)d_in[13];

    float* out = (float*)d_out;
    const size_t head_sz = (size_t)B_ * NH;
    float* out_pi     = out + 2 * head_sz;
    float* out_hidden = out + 3 * head_sz;

    __half *xh, *hidh, *i2dwh, *wihh, *whhh, *headwh, *h1h, *h2h, *houth;
    float  *gi, *gh;
    cudaGetSymbolAddress((void**)&xh,     g_xh);
    cudaGetSymbolAddress((void**)&hidh,   g_hidh);
    cudaGetSymbolAddress((void**)&i2dwh,  g_i2dwh);
    cudaGetSymbolAddress((void**)&wihh,   g_wihh);
    cudaGetSymbolAddress((void**)&whhh,   g_whhh);
    cudaGetSymbolAddress((void**)&headwh, g_headwh);
    cudaGetSymbolAddress((void**)&h1h,    g_h1h);
    cudaGetSymbolAddress((void**)&gi,     g_gi);
    cudaGetSymbolAddress((void**)&gh,     g_gh);
    cudaGetSymbolAddress((void**)&h2h,    g_h2h);
    cudaGetSymbolAddress((void**)&houth,  g_houth);

    const size_t lw = (size_t)3 * H_ * H_;
    const size_t lb = (size_t)3 * H_;
    const size_t lh = (size_t)B_ * H_;

    static bool attr_set = false;
    if (!attr_set) {
        cudaFuncSetAttribute(gemm_f16,
                             cudaFuncAttributeMaxDynamicSharedMemorySize, SMEM_BYTES);
        attr_set = true;
    }

    auto gemm = [&](const __half* A, const __half* W, const float* bias,
                    float* Cf, __half* Ch, int M, int N, int K, int act) {
        dim3 grid(N / BN, M / BM);
        gemm_f16<<<grid, 256, SMEM_BYTES>>>(A, W, bias, bias, bias, N,
                                            Cf, Ch, M, N, K, act);
    };

    const int gateGrid = (B_ * H_ / 4) / 256;
    const int smGrid   = (B_ * O_) / 256;

    // 1) ONE merged conversion launch: x, hidden, all weights -> half
    {
        ConvArgs ca;
        int e = 0, j = 0;
        auto add = [&](const float* s, __half* d, size_t n) {
            ca.src[j] = (const float4*)s;
            ca.dst[j] = (__half2*)d;
            e += (int)(n / 4);
            ca.end[j] = e;
            ++j;
        };
        add(x,       xh,     (size_t)B_ * IN_);
        add(hidden,  hidh,   (size_t)L_ * B_ * H_);
        add(i2d_w,   i2dwh,  (size_t)H_ * IN_);
        add(w_ih,    wihh,   (size_t)L_ * lw);
        add(w_hh,    whhh,   (size_t)L_ * lw);
        add(mu_w,    headwh,                       (size_t)NH * H_);
        add(sigma_w, headwh + (size_t)NH * H_,     (size_t)NH * H_);
        add(pi_w,    headwh + (size_t)2 * NH * H_, (size_t)NH * H_);
        conv_all_kernel<<<(e + 255) / 256, 256>>>(ca);
    }

    // 2) i2d: h1 = relu(x @ i2d_w^T + b) -> half
    gemm(xh, i2dwh, i2d_b, nullptr, h1h, B_, H_, IN_, 1);

    // 3,4,5) GRU layer 0
    gemm(hidh,      whhh,      b_hh,      gh, nullptr, B_, 3 * H_, H_, 0);
    gemm(h1h,       wihh,      b_ih,      gi, nullptr, B_, 3 * H_, H_, 0);
    gru_gate_kernel<<<gateGrid, 256>>>((const float4*)gi, (const float4*)gh,
                                       (const float4*)hidden,
                                       (float4*)out_hidden, (__half2*)h2h, nullptr);

    // 6,7,8) GRU layer 1  (launch #6 = gh1 GEMM -> ncu capture target)
    gemm(hidh + lh, whhh + lw, b_hh + lb, gh, nullptr, B_, 3 * H_, H_, 0);
    gemm(h2h,       wihh + lw, b_ih + lb, gi, nullptr, B_, 3 * H_, H_, 0);
    gru_gate_kernel<<<gateGrid, 256>>>((const float4*)gi, (const float4*)gh,
                                       (const float4*)(hidden + lh),
                                       (float4*)(out_hidden + lh), nullptr,
                                       (__half2*)houth);

    // 9) MDN heads: one fused GEMM (mu | sigma | pi), N = 2304
    {
        dim3 grid(NHEADS3 / BN, B_ / BM);
        gemm_f16<<<grid, 256, SMEM_BYTES>>>(houth, headwh,
                                            mu_b, sigma_b, pi_b, NH,
                                            out, nullptr, B_, NHEADS3, H_, 2);
    }

    // 10) pi softmax
    pi_softmax_kernel<<<smGrid, 256>>>(out_pi);
}

// round 8
// speedup vs baseline: 1.2632x; 1.0826x over previous
#include <cuda_runtime.h>
#include <cuda_fp16.h>
#include <math.h>
#include <stdint.h>

// ============================================================================
// Problem constants
// ============================================================================
#define B_  4096
#define IN_ 512
#define H_  1024
#define O_  256
#define L_  2
#define G_  3
#define NH  (G_ * O_)        // 768 per head
#define NHEADS3 (3 * NH)     // 2304 fused head columns

// ============================================================================
// GEMM tiling: m16n8k16 f16 mma.sync, ldmatrix, BK=64, 3-stage cp.async ring
// ============================================================================
#define BM 128
#define BN 128
#define BK 64
#define PH 72                           // smem pitch in halves (144 B rows)
#define ATB (BM * PH * 2)               // 18432 B per operand tile
#define STG_BYTES (2 * ATB)             // 36864 (A + W per stage)
#define NSTG 3
#define SMEM_BYTES (NSTG * STG_BYTES)   // 110592

// ============================================================================
// Scratch (device globals)
// ============================================================================
static __device__ __align__(256) __half g_xh    [(size_t)B_ * IN_];
static __device__ __align__(256) __half g_hidh  [(size_t)L_ * B_ * H_];
static __device__ __align__(256) __half g_i2dwh [(size_t)H_ * IN_];
static __device__ __align__(256) __half g_wihh  [(size_t)L_ * 3 * H_ * H_];
static __device__ __align__(256) __half g_whhh  [(size_t)L_ * 3 * H_ * H_];
static __device__ __align__(256) __half g_headwh[(size_t)NHEADS3 * H_];
static __device__ __align__(256) __half g_h1h   [(size_t)B_ * H_];
static __device__ __align__(256) float  g_gi    [(size_t)B_ * 3 * H_];
static __device__ __align__(256) float  g_gh    [(size_t)B_ * 3 * H_];
static __device__ __align__(256) __half g_h2h   [(size_t)B_ * H_];
static __device__ __align__(256) __half g_houth [(size_t)B_ * H_];

// ============================================================================
// PTX helpers
// ============================================================================
__device__ __forceinline__ void cp_async16(uint32_t saddr, const void* gptr) {
    asm volatile("cp.async.cg.shared.global [%0], [%1], 16;"
                 :: "r"(saddr), "l"(gptr) : "memory");
}
__device__ __forceinline__ void cp_commit() {
    asm volatile("cp.async.commit_group;" ::: "memory");
}
__device__ __forceinline__ void cp_wait2() {
    asm volatile("cp.async.wait_group 2;" ::: "memory");
}
__device__ __forceinline__ void cp_wait1() {
    asm volatile("cp.async.wait_group 1;" ::: "memory");
}
__device__ __forceinline__ void cp_wait0() {
    asm volatile("cp.async.wait_group 0;" ::: "memory");
}

#define LDSM4(r, a) \
    asm volatile("ldmatrix.sync.aligned.m8n8.x4.shared.b16 {%0,%1,%2,%3}, [%4];" \
        : "=r"((r)[0]), "=r"((r)[1]), "=r"((r)[2]), "=r"((r)[3]) : "r"(a))

__device__ __forceinline__ void mma_f16(float c[4], const uint32_t a[4],
                                        uint32_t b0, uint32_t b1) {
    asm volatile(
        "mma.sync.aligned.m16n8k16.row.col.f32.f16.f16.f32 "
        "{%0,%1,%2,%3}, {%4,%5,%6,%7}, {%8,%9}, {%0,%1,%2,%3};"
        : "+f"(c[0]), "+f"(c[1]), "+f"(c[2]), "+f"(c[3])
        : "r"(a[0]), "r"(a[1]), "r"(a[2]), "r"(a[3]), "r"(b0), "r"(b1));
}

__device__ __forceinline__ float tanha(float x) {
    float y;
    asm("tanh.approx.f32 %0, %1;" : "=f"(y) : "f"(x));
    return y;
}
__device__ __forceinline__ float sigma_f(float x) {
    return fmaf(0.5f, tanha(0.5f * x), 0.5f);
}

// ============================================================================
// Per-launch segment table (2 block-level segments: different A/W/bias/C)
// ============================================================================
struct Seg {
    const __half* A;
    const __half* W;
    const float*  b0;
    const float*  b1;
    const float*  b2;
    float*        Cf;
    __half*       Ch;
    int           act;     // 0 f32 out, 1 relu->half, 2 heads (softplus seg1)
};
struct GemmP {
    Seg s[2];
    int xTiles;            // N-tiles per segment
    int N;                 // columns per segment (C row stride)
    int K;
    int segN;              // column sub-segment width (for act==2 remap)
};

// ============================================================================
// GEMM: per segment  C[M,N] = A[M,K] @ W[N,K]^T + bias
// ============================================================================
__global__ __launch_bounds__(256, 2)
void gemm_f16(const __grid_constant__ GemmP p)
{
    extern __shared__ char smem_raw[];
    const uint32_t sbase = (uint32_t)__cvta_generic_to_shared(smem_raw);

    const int tid  = threadIdx.x;
    const int lane = tid & 31;
    const int wid  = tid >> 5;
    const int wm   = wid & 1;
    const int wn   = wid >> 1;

    const int segi = (blockIdx.x >= p.xTiles) ? 1 : 0;
    const int bn   = (blockIdx.x - segi * p.xTiles) * BN;
    const int bm   = blockIdx.y * BM;
    const Seg sg   = p.s[segi];
    const int K    = p.K;
    const int N    = p.N;

    float acc[4][4][4];
#pragma unroll
    for (int i = 0; i < 4; ++i)
#pragma unroll
        for (int j = 0; j < 4; ++j)
#pragma unroll
            for (int q = 0; q < 4; ++q) acc[i][j][q] = 0.f;

    // cp.async: 4 x 16B per thread for A and for W per stage (BK=64)
    const __half* __restrict__ Ap = sg.A;
    const __half* __restrict__ Wp = sg.W;
    auto issue = [&](int stg, int kt) {
        uint32_t sa = sbase + stg * STG_BYTES;
        uint32_t sb = sa + ATB;
#pragma unroll
        for (int i = 0; i < 4; ++i) {
            int idx = tid + i * 256;
            int row = idx >> 3;
            int c8  = (idx & 7) << 3;
            uint32_t doff = (uint32_t)(row * PH + c8) * 2;
            cp_async16(sa + doff, Ap + (size_t)(bm + row) * K + kt + c8);
            cp_async16(sb + doff, Wp + (size_t)(bn + row) * K + kt + c8);
        }
        cp_commit();
    };

    const int nT = K / BK;               // 8 (K=512) or 16 (K=1024)
    issue(0, 0);
    issue(1, BK);
    issue(2, 2 * BK);

    // ldmatrix lane addressing (pitch PH halves)
    const uint32_t aOff = (uint32_t)(((wm * 64 + (lane & 15)) * PH +
                                      ((lane >> 4) << 3)) * 2);
    const uint32_t bOff = (uint32_t)(((wn * 32 + ((lane >> 4) << 3) + (lane & 7)) * PH +
                                      (((lane >> 3) & 1) << 3)) * 2);

    uint32_t afb[2][4][4];
    uint32_t bfb[2][2][4];

    auto ldsm_half = [&](int s, int kk, int bsel) {
        uint32_t sa = sbase + s * STG_BYTES;
        uint32_t sb = sa + ATB;
#pragma unroll
        for (int mt = 0; mt < 4; ++mt)
            LDSM4(afb[bsel][mt], sa + aOff + (uint32_t)(mt * 16 * PH + kk) * 2);
#pragma unroll
        for (int pq = 0; pq < 2; ++pq)
            LDSM4(bfb[bsel][pq], sb + bOff + (uint32_t)(pq * 16 * PH + kk) * 2);
    };
    auto mma_half = [&](int bsel) {
#pragma unroll
        for (int mt = 0; mt < 4; ++mt)
#pragma unroll
            for (int nt = 0; nt < 4; ++nt)
                mma_f16(acc[mt][nt], afb[bsel][mt],
                        bfb[bsel][nt >> 1][(nt & 1) * 2],
                        bfb[bsel][nt >> 1][(nt & 1) * 2 + 1]);
    };

    // Prologue: stage 0 ready (2 groups may stay outstanding)
    cp_wait2();
    __syncthreads();
    ldsm_half(0, 0, 0);

    for (int t = 0; t < nT; ++t) {
        const int s = t % NSTG;
        // 4 half-tiles (kk = 0,16,32,48), fragment double-buffered
        ldsm_half(s, 16, 1);
        mma_half(0);
        ldsm_half(s, 32, 0);
        mma_half(1);
        ldsm_half(s, 48, 1);
        mma_half(0);
        if (t + 1 < nT) {
            if (t == nT - 2) cp_wait0(); else cp_wait1();
            __syncthreads();
            if (t + 3 < nT) issue((t + 3) % NSTG, (t + 3) * BK);
            ldsm_half((t + 1) % NSTG, 0, 0);
        }
        mma_half(1);
    }

    // ---- Epilogue ----
    const int lgrp = lane >> 2;
    const int lth  = lane & 3;
    const int act  = sg.act;
#pragma unroll
    for (int nt = 0; nt < 4; ++nt) {
        int col  = bn + wn * 32 + nt * 8 + 2 * lth;
        int cseg = col / p.segN;        // column sub-segment (heads only)
        int lcol = col - cseg * p.segN;
        const float* bp = (cseg == 0) ? sg.b0 : (cseg == 1) ? sg.b1 : sg.b2;
        float bx = __ldg(bp + lcol);
        float by = __ldg(bp + lcol + 1);
#pragma unroll
        for (int mt = 0; mt < 4; ++mt) {
            int row = bm + wm * 64 + mt * 16 + lgrp;
            float v0x = acc[mt][nt][0] + bx, v0y = acc[mt][nt][1] + by;
            float v1x = acc[mt][nt][2] + bx, v1y = acc[mt][nt][3] + by;
            if (act == 1) {
                __half2 h0 = __floats2half2_rn(fmaxf(v0x, 0.f), fmaxf(v0y, 0.f));
                __half2 h1 = __floats2half2_rn(fmaxf(v1x, 0.f), fmaxf(v1y, 0.f));
                *reinterpret_cast<__half2*>(sg.Ch + (size_t)row * N + col)       = h0;
                *reinterpret_cast<__half2*>(sg.Ch + (size_t)(row + 8) * N + col) = h1;
            } else if (act == 0) {
                *reinterpret_cast<float2*>(sg.Cf + (size_t)row * N + col)       = make_float2(v0x, v0y);
                *reinterpret_cast<float2*>(sg.Cf + (size_t)(row + 8) * N + col) = make_float2(v1x, v1y);
            } else {
                if (cseg == 1) {         // softplus for sigma head
                    v0x = (v0x > 20.f) ? v0x : log1pf(__expf(v0x));
                    v0y = (v0y > 20.f) ? v0y : log1pf(__expf(v0y));
                    v1x = (v1x > 20.f) ? v1x : log1pf(__expf(v1x));
                    v1y = (v1y > 20.f) ? v1y : log1pf(__expf(v1y));
                }
                float* dst = sg.Cf + (size_t)cseg * ((size_t)B_ * NH)
                                   + (size_t)row * NH + lcol;
                *reinterpret_cast<float2*>(dst)                  = make_float2(v0x, v0y);
                *reinterpret_cast<float2*>(dst + (size_t)8 * NH) = make_float2(v1x, v1y);
            }
        }
    }
}

// ============================================================================
// f32 -> f16 conversion (batched pointer table, up to 4 tensors per launch)
// ============================================================================
struct ConvArgs {
    const float4* src[4];
    __half2*      dst[4];
    int           end[4];
};

__global__ void conv_kernel(const __grid_constant__ ConvArgs a)
{
    int i = blockIdx.x * blockDim.x + threadIdx.x;
    int prev = 0;
#pragma unroll
    for (int j = 0; j < 4; ++j) {
        if (i < a.end[j]) {
            int k = i - prev;
            float4 v = a.src[j][k];
            a.dst[j][2 * k]     = __floats2half2_rn(v.x, v.y);
            a.dst[j][2 * k + 1] = __floats2half2_rn(v.z, v.w);
            return;
        }
        prev = a.end[j];
    }
}

// ============================================================================
// GRU gate fusion (HW tanh.approx)
// ============================================================================
__global__ void gru_gate_kernel(const float4* __restrict__ gi,
                                const float4* __restrict__ gh,
                                const float4* __restrict__ hprev,
                                float4* __restrict__ hnew,
                                __half2* __restrict__ hh,
                                __half2* __restrict__ htanhh)
{
    int idx = blockIdx.x * blockDim.x + threadIdx.x;
    if (idx >= B_ * H_ / 4) return;
    int b  = idx >> 8;
    int jj = idx & 255;
    const float4* gib = gi + (size_t)b * (3 * H_ / 4);
    const float4* ghb = gh + (size_t)b * (3 * H_ / 4);
    float4 ir = gib[jj], iz = gib[256 + jj], in_ = gib[512 + jj];
    float4 hr = ghb[jj], hz = ghb[256 + jj], hn  = ghb[512 + jj];
    float4 hp = hprev[idx];
    float4 h;
    {
        float r = sigma_f(ir.x + hr.x), z = sigma_f(iz.x + hz.x);
        float n = tanha(fmaf(r, hn.x, in_.x));
        h.x = fmaf(z, hp.x - n, n);
    }
    {
        float r = sigma_f(ir.y + hr.y), z = sigma_f(iz.y + hz.y);
        float n = tanha(fmaf(r, hn.y, in_.y));
        h.y = fmaf(z, hp.y - n, n);
    }
    {
        float r = sigma_f(ir.z + hr.z), z = sigma_f(iz.z + hz.z);
        float n = tanha(fmaf(r, hn.z, in_.z));
        h.z = fmaf(z, hp.z - n, n);
    }
    {
        float r = sigma_f(ir.w + hr.w), z = sigma_f(iz.w + hz.w);
        float n = tanha(fmaf(r, hn.w, in_.w));
        h.w = fmaf(z, hp.w - n, n);
    }
    hnew[idx] = h;
    if (hh) {
        hh[2 * idx]     = __floats2half2_rn(h.x, h.y);
        hh[2 * idx + 1] = __floats2half2_rn(h.z, h.w);
    }
    if (htanhh) {
        htanhh[2 * idx]     = __floats2half2_rn(tanha(h.x), tanha(h.y));
        htanhh[2 * idx + 1] = __floats2half2_rn(tanha(h.z), tanha(h.w));
    }
}

__global__ void pi_softmax_kernel(float* __restrict__ pi)
{
    int idx = blockIdx.x * blockDim.x + threadIdx.x;
    if (idx >= B_ * O_) return;
    int b = idx >> 8;
    int o = idx & (O_ - 1);
    float* p = pi + (size_t)b * NH + o;
    float v0 = p[0], v1 = p[O_], v2 = p[2 * O_];
    float m = fmaxf(v0, fmaxf(v1, v2));
    float e0 = __expf(v0 - m), e1 = __expf(v1 - m), e2 = __expf(v2 - m);
    float inv = 1.f / (e0 + e1 + e2);
    p[0] = e0 * inv; p[O_] = e1 * inv; p[2 * O_] = e2 * inv;
}

// ============================================================================
// Host
// ============================================================================
extern "C" void kernel_launch(void* const* d_in, const int* in_sizes, int n_in,
                              void* d_out, int out_size)
{
    const float* x       = (const float*)d_in[0];
    const float* hidden  = (const float*)d_in[1];
    const float* i2d_w   = (const float*)d_in[2];
    const float* i2d_b   = (const float*)d_in[3];
    const float* w_ih    = (const float*)d_in[4];
    const float* w_hh    = (const float*)d_in[5];
    const float* b_ih    = (const float*)d_in[6];
    const float* b_hh    = (const float*)d_in[7];
    const float* mu_w    = (const float*)d_in[8];
    const float* mu_b    = (const float*)d_in[9];
    const float* sigma_w = (const float*)d_in[10];
    const float* sigma_b = (const float*)d_in[11];
    const float* pi_w    = (const float*)d_in[12];
    const float* pi_b    = (const float*)d_in[13];

    float* out = (float*)d_out;
    const size_t head_sz = (size_t)B_ * NH;
    float* out_pi     = out + 2 * head_sz;
    float* out_hidden = out + 3 * head_sz;

    __half *xh, *hidh, *i2dwh, *wihh, *whhh, *headwh, *h1h, *h2h, *houth;
    float  *gi, *gh;
    cudaGetSymbolAddress((void**)&xh,     g_xh);
    cudaGetSymbolAddress((void**)&hidh,   g_hidh);
    cudaGetSymbolAddress((void**)&i2dwh,  g_i2dwh);
    cudaGetSymbolAddress((void**)&wihh,   g_wihh);
    cudaGetSymbolAddress((void**)&whhh,   g_whhh);
    cudaGetSymbolAddress((void**)&headwh, g_headwh);
    cudaGetSymbolAddress((void**)&h1h,    g_h1h);
    cudaGetSymbolAddress((void**)&gi,     g_gi);
    cudaGetSymbolAddress((void**)&gh,     g_gh);
    cudaGetSymbolAddress((void**)&h2h,    g_h2h);
    cudaGetSymbolAddress((void**)&houth,  g_houth);

    const size_t lw = (size_t)3 * H_ * H_;
    const size_t lb = (size_t)3 * H_;
    const size_t lh = (size_t)B_ * H_;

    static bool attr_set = false;
    if (!attr_set) {
        cudaFuncSetAttribute(gemm_f16,
                             cudaFuncAttributeMaxDynamicSharedMemorySize, SMEM_BYTES);
        attr_set = true;
    }

    const int gateGrid = (B_ * H_ / 4) / 256;
    const int smGrid   = (B_ * O_) / 256;

    // ---- 1,2) conversion prepass (two launches, 4 tensors each) ----
    {
        ConvArgs ca;
        int e = 0, j = 0;
        auto add = [&](const float* s, __half* d, size_t n) {
            ca.src[j] = (const float4*)s;
            ca.dst[j] = (__half2*)d;
            e += (int)(n / 4);
            ca.end[j] = e;
            ++j;
        };
        add(x,      xh,    (size_t)B_ * IN_);
        add(hidden, hidh,  (size_t)L_ * B_ * H_);
        add(i2d_w,  i2dwh, (size_t)H_ * IN_);
        add(w_ih,   wihh,  (size_t)L_ * lw);
        conv_kernel<<<(e + 255) / 256, 256>>>(ca);
    }
    {
        ConvArgs ca;
        int e = 0, j = 0;
        auto add = [&](const float* s, __half* d, size_t n) {
            ca.src[j] = (const float4*)s;
            ca.dst[j] = (__half2*)d;
            e += (int)(n / 4);
            ca.end[j] = e;
            ++j;
        };
        add(w_hh,    whhh,  (size_t)L_ * lw);
        add(mu_w,    headwh,                       (size_t)NH * H_);
        add(sigma_w, headwh + (size_t)NH * H_,     (size_t)NH * H_);
        add(pi_w,    headwh + (size_t)2 * NH * H_, (size_t)NH * H_);
        conv_kernel<<<(e + 255) / 256, 256>>>(ca);
    }

    // ---- 3) i2d: h1 = relu(x @ i2d_w^T + b) -> half ----
    {
        GemmP p;
        p.s[0] = { xh, i2dwh, i2d_b, i2d_b, i2d_b, nullptr, h1h, 1 };
        p.s[1] = p.s[0];
        p.xTiles = H_ / BN; p.N = H_; p.K = IN_; p.segN = H_;
        gemm_f16<<<dim3(p.xTiles, B_ / BM), 256, SMEM_BYTES>>>(p);
    }

    // ---- 4) GRU layer 0: gh | gi fused (one launch, 2 segments) ----
    {
        GemmP p;
        p.s[0] = { hidh, whhh, b_hh, b_hh, b_hh, gh, nullptr, 0 };
        p.s[1] = { h1h,  wihh, b_ih, b_ih, b_ih, gi, nullptr, 0 };
        p.xTiles = 3 * H_ / BN; p.N = 3 * H_; p.K = H_; p.segN = 3 * H_;
        gemm_f16<<<dim3(2 * p.xTiles, B_ / BM), 256, SMEM_BYTES>>>(p);
    }
    // ---- 5) gate 0 ----
    gru_gate_kernel<<<gateGrid, 256>>>((const float4*)gi, (const float4*)gh,
                                       (const float4*)hidden,
                                       (float4*)out_hidden, (__half2*)h2h, nullptr);

    // ---- 6) GRU layer 1: gh | gi fused  (ncu capture target) ----
    {
        GemmP p;
        p.s[0] = { hidh + lh, whhh + lw, b_hh + lb, b_hh + lb, b_hh + lb, gh, nullptr, 0 };
        p.s[1] = { h2h,       wihh + lw, b_ih + lb, b_ih + lb, b_ih + lb, gi, nullptr, 0 };
        p.xTiles = 3 * H_ / BN; p.N = 3 * H_; p.K = H_; p.segN = 3 * H_;
        gemm_f16<<<dim3(2 * p.xTiles, B_ / BM), 256, SMEM_BYTES>>>(p);
    }
    // ---- 7) gate 1 ----
    gru_gate_kernel<<<gateGrid, 256>>>((const float4*)gi, (const float4*)gh,
                                       (const float4*)(hidden + lh),
                                       (float4*)(out_hidden + lh), nullptr,
                                       (__half2*)houth);

    // ---- 8) MDN heads: one fused GEMM (mu | sigma | pi), N = 2304 ----
    {
        GemmP p;
        p.s[0] = { houth, headwh, mu_b, sigma_b, pi_b, out, nullptr, 2 };
        p.s[1] = p.s[0];
        p.xTiles = NHEADS3 / BN; p.N = NHEADS3; p.K = H_; p.segN = NH;
        gemm_f16<<<dim3(p.xTiles, B_ / BM), 256, SMEM_BYTES>>>(p);
    }

    // ---- 9) pi softmax ----
    pi_softmax_kernel<<<smGrid, 256>>>(out_pi);
}